// round 11
// baseline (speedup 1.0000x reference)
#include <cuda_runtime.h>
#include <cuda_bf16.h>
#include <cstdint>

#define IMG   4096
#define OUT   4097
#define TX    128
#define TY    32
#define HP    (TX + 3)   // 131  hist-tile pitch (u64)
#define HR    (TY + 3)   // 35   hist-tile rows
#define NG    33         // 4-pixel groups per hist row (last group is width 3)
#define OPLANE (OUT * OUT)
#define HTY   (TY / 2)

typedef unsigned long long u64;
typedef unsigned int       u32;

// predicated packed add: if (pm == P) acc += v  (two fp32 lanes at once)
#define PRED_ADD2(acc, pm, P, v)                                              \
    asm("{ .reg .pred p; setp.eq.u32 p, %1, %2; @p add.rn.f32x2 %0, %0, %3; }" \
        : "+l"(acc) : "r"(pm), "n"(P), "l"(v))

#define ADD2(d, a, b)                                                         \
    asm("add.rn.f32x2 %0, %1, %2;" : "=l"(d) : "l"(a), "l"(b))

#define FMA2(d, a, b, c)                                                      \
    asm("fma.rn.f32x2 %0, %1, %2, %3;" : "=l"(d) : "l"(a), "l"(b), "l"(c))

// route one hist row (4 packed pixels) into rs[4] (accumulating)
static __device__ __forceinline__ void accum_row(const u64* __restrict__ p, u64 rs[4]) {
#pragma unroll
    for (int j = 0; j < 4; ++j) {
        u64 h  = p[j];
        u32 pm = (u32)h & 3u;           // pair index in low 2 bits of lo lane
        PRED_ADD2(rs[0], pm, 0, h);
        PRED_ADD2(rs[1], pm, 1, h);
        PRED_ADD2(rs[2], pm, 2, h);
        PRED_ADD2(rs[3], pm, 3, h);
    }
}

// mag/octant/pack from gradients
static __device__ __forceinline__ u64 pack_grad(float dx, float dy) {
    float sq = dx * dx + dy * dy;
    float sg = fmaxf(sq, 1.17549435e-38f);
    float rs_;
    asm("rsqrt.approx.f32 %0, %1;" : "=f"(rs_) : "f"(sg));
    float mag = sq * rs_;

    // octant of atan2(dy,dx) via sign bits + |dy|>|dx|; tie rules match
    // strict-> first-occurrence argmax of the 8 cosine projections.
    u32 bx = __float_as_uint(dx);
    u32 by = __float_as_uint(dy);
    u32 b2 = by >> 31;
    u32 b1 = (bx ^ by) >> 31;
    u32 c  = (fabsf(dy) > fabsf(dx)) ? 1u : 0u;
    u32 b0 = c ^ b1;
    u32 idx = (b2 << 2) | (b1 << 1) | b0;

    u32 magb = __float_as_uint(mag) & 0xFFFFFFFCu;
    u32 pm   = idx >> 1;
    u32 lo, hi;
    if (idx & 1) { lo = pm;        hi = magb; }
    else         { lo = magb | pm; hi = 0u;   }
    return ((u64)hi << 32) | lo;
}

static __device__ __forceinline__ float ldz(const float* __restrict__ x, int gy, int gx) {
    return ((unsigned)gy < (unsigned)IMG && (unsigned)gx < (unsigned)IMG)
           ? x[gy * IMG + gx] : 0.0f;
}

__global__ __launch_bounds__(256, 5)
void sift_fused11_kernel(const float* __restrict__ x, float* __restrict__ out)
{
    __shared__ u64 hs[HR * HP];   // 36,680 B -> 5 CTAs/SM

    const int tid = threadIdx.x;
    const int ox0 = blockIdx.x * TX;
    const int oy0 = blockIdx.y * TY;

    // ---- phase 2 (no staging): sobel straight from GMEM via aligned float4 groups.
    // Group (hy, g): pixels hx..hx+3 (hx = 4g); loads x cols ox0-4+hx .. +7,
    // rows oy0-3+hy .. +2 — all 16B-aligned (ox0, hx multiples of 4).
    const bool interior = (ox0 >= 4) && (ox0 + TX + 4 <= IMG) &&
                          (oy0 >= 3) && (oy0 + TY + 2 <= IMG);
    if (interior) {
        for (int e = tid; e < HR * NG; e += 256) {
            int hy = e / NG;
            int g  = e - hy * NG;
            int hx = g * 4;

            const float* pb = x + (oy0 - 3 + hy) * IMG + (ox0 - 4 + hx);
            float S[6], D[6];
            {
                float4 L = *(const float4*)(pb);
                float4 R = *(const float4*)(pb + 4);
                S[0] = L.y; S[1] = L.z; S[2] = L.w; S[3] = R.x; S[4] = R.y; S[5] = R.z;
                L = *(const float4*)(pb + IMG);
                R = *(const float4*)(pb + IMG + 4);
                float m0 = L.y, m1 = L.z, m2 = L.w, m3 = R.x, m4 = R.y, m5 = R.z;
                L = *(const float4*)(pb + 2 * IMG);
                R = *(const float4*)(pb + 2 * IMG + 4);
                D[0] = L.y - S[0]; D[1] = L.z - S[1]; D[2] = L.w - S[2];
                D[3] = R.x - S[3]; D[4] = R.y - S[4]; D[5] = R.z - S[5];
                S[0] += 2.0f * m0 + L.y; S[1] += 2.0f * m1 + L.z; S[2] += 2.0f * m2 + L.w;
                S[3] += 2.0f * m3 + R.x; S[4] += 2.0f * m4 + R.y; S[5] += 2.0f * m5 + R.z;
            }

            u64* hp = hs + hy * HP + hx;
#pragma unroll
            for (int k = 0; k < 4; ++k) {
                float dx = S[k + 2] - S[k];
                float dy = D[k] + 2.0f * D[k + 1] + D[k + 2];
                u64 pv = pack_grad(dx, dy);
                if (k < 3 || hx + 3 < HP) hp[k] = pv;   // last group is width 3
            }
        }
    } else {
        for (int e = tid; e < HR * HP; e += 256) {
            int hy = e / HP;
            int hx = e - hy * HP;
            int gy = oy0 - 2 + hy;
            int gx = ox0 - 2 + hx;
            u64 pv = 0ull;
            if ((unsigned)gy < (unsigned)IMG && (unsigned)gx < (unsigned)IMG) {
                float a00 = ldz(x, gy - 1, gx - 1), a01 = ldz(x, gy - 1, gx), a02 = ldz(x, gy - 1, gx + 1);
                float a10 = ldz(x, gy,     gx - 1),                           a12 = ldz(x, gy,     gx + 1);
                float a20 = ldz(x, gy + 1, gx - 1), a21 = ldz(x, gy + 1, gx), a22 = ldz(x, gy + 1, gx + 1);
                float S0 = a00 + 2.0f * a10 + a20;
                float S2 = a02 + 2.0f * a12 + a22;
                float dx = S2 - S0;
                float dy = (a20 - a00) + 2.0f * (a21 - a01) + (a22 - a02);
                pv = pack_grad(dx, dy);
            }
            hs[e] = pv;
        }
    }
    __syncthreads();

    // ---- phase 3: 4x4 box sum, vertical sliding window, 4 packed-pair channels
    const int tx   = tid & (TX - 1);
    const int q    = tid >> 7;              // 0/1 -> tile half in y
    const int ox   = ox0 + tx;
    const int oy_s = oy0 + q * HTY;
    const bool oxok = (ox < OUT);
    const u64* hb = hs + tx;
    const int hy0 = q * HTY;

    const u64 NEG1 = 0xBF800000BF800000ull;  // {-1.0f, -1.0f}

    u64 row[4][4];
    u64 acc[4];
#pragma unroll
    for (int pp = 0; pp < 4; ++pp) acc[pp] = 0ull;
#pragma unroll
    for (int k = 0; k < 4; ++k) {
#pragma unroll
        for (int pp = 0; pp < 4; ++pp) row[k][pp] = 0ull;
        accum_row(hb + (hy0 + k) * HP, row[k]);
#pragma unroll
        for (int pp = 0; pp < 4; ++pp) ADD2(acc[pp], acc[pp], row[k][pp]);
    }

#pragma unroll 4
    for (int i = 0; i < HTY; ++i) {
        int oy = oy_s + i;
        if (oxok && oy < OUT) {
            int base = oy * OUT + ox;
#pragma unroll
            for (int pp = 0; pp < 4; ++pp) {
                u32 lo = (u32)acc[pp];
                u32 hi = (u32)(acc[pp] >> 32);
                out[(2 * pp)     * OPLANE + base] = __uint_as_float(lo);
                out[(2 * pp + 1) * OPLANE + base] = __uint_as_float(hi);
            }
        }
        if (i < HTY - 1) {
            u64 nr[4];
#pragma unroll
            for (int pp = 0; pp < 4; ++pp) nr[pp] = 0ull;
            accum_row(hb + (hy0 + 4 + i) * HP, nr);
            const int k = i & 3;
#pragma unroll
            for (int pp = 0; pp < 4; ++pp) {
                u64 t;
                ADD2(t, acc[pp], nr[pp]);            // acc + new
                FMA2(acc[pp], row[k][pp], NEG1, t);  // - old
                row[k][pp] = nr[pp];
            }
        }
    }
}

extern "C" void kernel_launch(void* const* d_in, const int* in_sizes, int n_in,
                              void* d_out, int out_size)
{
    (void)in_sizes; (void)n_in; (void)out_size;
    const float* x = (const float*)d_in[0];
    float* out = (float*)d_out;
    dim3 grid((OUT + TX - 1) / TX, (OUT + TY - 1) / TY);  // 33 x 129
    sift_fused11_kernel<<<grid, 256>>>(x, out);
}

// round 12
// speedup vs baseline: 1.1309x; 1.1309x over previous
#include <cuda_runtime.h>
#include <cuda_bf16.h>
#include <cstdint>

#define IMG   4096
#define OUT   4097
#define TX    128
#define TY    32
#define XP2   136        // x-tile pitch (floats), padded for float4
#define XR    37         // x-tile rows
#define HP    (TX + 3)   // 131  hist-tile pitch (u32)
#define HR    (TY + 3)   // 35   hist-tile rows
#define OPLANE (OUT * OUT)
#define HTY   (TY / 2)

typedef unsigned long long u64;
typedef unsigned int       u32;

// predicated packed add: if (pm6 == P) acc += v  (two fp32 lanes at once)
#define PRED_ADD2(acc, pm6, P, v)                                             \
    asm("{ .reg .pred p; setp.eq.u32 p, %1, %2; @p add.rn.f32x2 %0, %0, %3; }" \
        : "+l"(acc) : "r"(pm6), "n"(P), "l"(v))

#define ADD2(d, a, b)                                                         \
    asm("add.rn.f32x2 %0, %1, %2;" : "=l"(d) : "l"(a), "l"(b))

#define FMA2(d, a, b, c)                                                      \
    asm("fma.rn.f32x2 %0, %1, %2, %3;" : "=l"(d) : "l"(a), "l"(b), "l"(c))

#define PACK64(v, lo, hi)                                                     \
    asm("mov.b64 %0, {%1, %2};" : "=l"(v) : "r"(lo), "r"(hi))

// route one hist row (4 u32 pixels) into rs[4] packed-pair accumulators
static __device__ __forceinline__ void accum_row(const u32* __restrict__ p, u64 rs[4]) {
#pragma unroll
    for (int j = 0; j < 4; ++j) {
        u32 h    = p[j];
        u32 magb = h & 0xFFFFFFF8u;
        u32 lo   = (h & 1u) ? 0u   : magb;
        u32 hi   = (h & 1u) ? magb : 0u;
        u64 v;  PACK64(v, lo, hi);
        u32 pm6  = h & 6u;              // 2*pair index
        PRED_ADD2(rs[0], pm6, 0, v);
        PRED_ADD2(rs[1], pm6, 2, v);
        PRED_ADD2(rs[2], pm6, 4, v);
        PRED_ADD2(rs[3], pm6, 6, v);
    }
}

// sobel + octant + pack for one hist element; p = top-left of 3x3 in xs
static __device__ __forceinline__ u32 hist_val(const float* __restrict__ p) {
    float a00 = p[0],       a01 = p[1],           a02 = p[2];
    float a10 = p[XP2],     a12 = p[XP2 + 2];
    float a20 = p[2 * XP2], a21 = p[2 * XP2 + 1], a22 = p[2 * XP2 + 2];
    float S0 = a00 + 2.0f * a10 + a20;
    float S2 = a02 + 2.0f * a12 + a22;
    float D0 = a20 - a00;
    float D1 = a21 - a01;
    float D2 = a22 - a02;
    float dx = S2 - S0;
    float dy = D0 + 2.0f * D1 + D2;

    float sq = dx * dx + dy * dy;
    float sg = fmaxf(sq, 1.17549435e-38f);
    float rs_;
    asm("rsqrt.approx.f32 %0, %1;" : "=f"(rs_) : "f"(sg));
    float mag = sq * rs_;

    // octant of atan2(dy,dx) via sign bits + |dy|>|dx|; tie rules match
    // strict-> first-occurrence argmax of the 8 cosine projections.
    u32 bx = __float_as_uint(dx);
    u32 by = __float_as_uint(dy);
    u32 b2 = by >> 31;
    u32 b1 = (bx ^ by) >> 31;
    u32 c  = (fabsf(dy) > fabsf(dx)) ? 1u : 0u;
    u32 b0 = c ^ b1;
    u32 idx = (b2 << 2) | (b1 << 1) | b0;

    return (__float_as_uint(mag) & 0xFFFFFFF8u) | idx;
}

__global__ __launch_bounds__(256, 5)
void sift_fused12_kernel(const float* __restrict__ x, float* __restrict__ out)
{
    __shared__ float xs[XR * XP2];   // 20,128 B
    __shared__ u32   hs[HR * HP];    // 18,340 B   -> total 38.5 KB -> 5 CTAs/SM

    const int tid = threadIdx.x;
    const int ox0 = blockIdx.x * TX;
    const int oy0 = blockIdx.y * TY;

    // ---- phase 1: load x tile (cols gx = ox0-4+c, rows gy = oy0-3+r), zero-padded
    const bool ld_interior = (ox0 >= 4) && (ox0 <= IMG - 132) &&
                             (oy0 >= 3) && (oy0 <= IMG - 34);
    if (ld_interior) {
        const float* xb = x + (oy0 - 3) * IMG + (ox0 - 4);   // 16B-aligned
#pragma unroll 5
        for (int e = tid; e < XR * 34; e += 256) {
            int r  = e / 34;
            int c4 = e - r * 34;
            float4 v = *(const float4*)(xb + r * IMG + 4 * c4);
            *(float4*)&xs[r * XP2 + 4 * c4] = v;
        }
    } else {
        for (int e = tid; e < XR * XP2; e += 256) {
            int r  = e / XP2;
            int c  = e - r * XP2;
            int gy = oy0 - 3 + r;
            int gx = ox0 - 4 + c;
            float v = 0.0f;
            if ((unsigned)gy < (unsigned)IMG && (unsigned)gx < (unsigned)IMG)
                v = x[gy * IMG + gx];
            xs[r * XP2 + c] = v;
        }
    }
    __syncthreads();

    // ---- phase 2: sobel -> octant -> u32 (mag | idx)
    const bool h_interior = (ox0 >= 2) && (ox0 + TX + 2 < IMG) &&
                            (oy0 >= 2) && (oy0 + TY + 2 < IMG);
    if (h_interior) {
        for (int e = tid; e < HR * HP; e += 256) {
            int hy = e / HP;
            int hx = e - hy * HP;
            hs[e] = hist_val(xs + hy * XP2 + hx + 1);
        }
    } else {
        for (int e = tid; e < HR * HP; e += 256) {
            int hy = e / HP;
            int hx = e - hy * HP;
            int gy = oy0 - 2 + hy;
            int gx = ox0 - 2 + hx;
            u32 pv = 0u;
            if ((unsigned)gy < (unsigned)IMG && (unsigned)gx < (unsigned)IMG)
                pv = hist_val(xs + hy * XP2 + hx + 1);
            hs[e] = pv;
        }
    }
    __syncthreads();

    // ---- phase 3: 4x4 box sum, vertical sliding window, 4 packed-pair channels
    const int tx   = tid & (TX - 1);
    const int q    = tid >> 7;              // 0/1 -> tile half in y
    const int ox   = ox0 + tx;
    const int oy_s = oy0 + q * HTY;
    const bool oxok = (ox < OUT);
    const u32* hb = hs + tx;
    const int hy0 = q * HTY;

    const u64 NEG1 = 0xBF800000BF800000ull;  // {-1.0f, -1.0f}

    u64 row[4][4];
    u64 acc[4];
#pragma unroll
    for (int pp = 0; pp < 4; ++pp) acc[pp] = 0ull;
#pragma unroll
    for (int k = 0; k < 4; ++k) {
#pragma unroll
        for (int pp = 0; pp < 4; ++pp) row[k][pp] = 0ull;
        accum_row(hb + (hy0 + k) * HP, row[k]);
#pragma unroll
        for (int pp = 0; pp < 4; ++pp) ADD2(acc[pp], acc[pp], row[k][pp]);
    }

#pragma unroll 4
    for (int i = 0; i < HTY; ++i) {
        int oy = oy_s + i;
        if (oxok && oy < OUT) {
            int base = oy * OUT + ox;
#pragma unroll
            for (int pp = 0; pp < 4; ++pp) {
                u32 lo = (u32)acc[pp];
                u32 hi = (u32)(acc[pp] >> 32);
                out[(2 * pp)     * OPLANE + base] = __uint_as_float(lo);
                out[(2 * pp + 1) * OPLANE + base] = __uint_as_float(hi);
            }
        }
        if (i < HTY - 1) {
            u64 nr[4];
#pragma unroll
            for (int pp = 0; pp < 4; ++pp) nr[pp] = 0ull;
            accum_row(hb + (hy0 + 4 + i) * HP, nr);
            const int k = i & 3;
#pragma unroll
            for (int pp = 0; pp < 4; ++pp) {
                u64 t;
                ADD2(t, acc[pp], nr[pp]);            // acc + new
                FMA2(acc[pp], row[k][pp], NEG1, t);  // - old
                row[k][pp] = nr[pp];
            }
        }
    }
}

extern "C" void kernel_launch(void* const* d_in, const int* in_sizes, int n_in,
                              void* d_out, int out_size)
{
    (void)in_sizes; (void)n_in; (void)out_size;
    const float* x = (const float*)d_in[0];
    float* out = (float*)d_out;
    dim3 grid((OUT + TX - 1) / TX, (OUT + TY - 1) / TY);  // 33 x 129
    sift_fused12_kernel<<<grid, 256>>>(x, out);
}

// round 13
// speedup vs baseline: 1.6436x; 1.4534x over previous
#include <cuda_runtime.h>
#include <cuda_bf16.h>
#include <cstdint>

#define IMG   4096
#define OUT   4097
#define TX    128
#define TY    32
#define XP2   136        // x-tile pitch (floats), padded for float4 (= 4*34)
#define XR    37         // x-tile rows
#define HP    (TX + 3)   // 131  hist-tile pitch (u64)
#define HR    (TY + 3)   // 35   hist-tile rows
#define OPLANE (OUT * OUT)
#define HTY   (TY / 2)

#define XS_BYTES  (XR * XP2 * 4)                  // 20128, 16B-aligned
#define SMEM_BYTES (XS_BYTES + HR * HP * 8)       // ~55.5 KB

typedef unsigned long long u64;
typedef unsigned int       u32;

// predicated packed add: if (pm == P) acc += v  (two fp32 lanes at once)
#define PRED_ADD2(acc, pm, P, v)                                              \
    asm("{ .reg .pred p; setp.eq.u32 p, %1, %2; @p add.rn.f32x2 %0, %0, %3; }" \
        : "+l"(acc) : "r"(pm), "n"(P), "l"(v))

#define ADD2(d, a, b)                                                         \
    asm("add.rn.f32x2 %0, %1, %2;" : "=l"(d) : "l"(a), "l"(b))

#define FMA2(d, a, b, c)                                                      \
    asm("fma.rn.f32x2 %0, %1, %2, %3;" : "=l"(d) : "l"(a), "l"(b), "l"(c))

// route one hist row (4 packed pixels) into rs[4] (accumulating)
static __device__ __forceinline__ void accum_row(const u64* __restrict__ p, u64 rs[4]) {
#pragma unroll
    for (int j = 0; j < 4; ++j) {
        u64 h  = p[j];
        u32 pm = (u32)h & 3u;           // pair index in low 2 bits of lo lane
        PRED_ADD2(rs[0], pm, 0, h);
        PRED_ADD2(rs[1], pm, 1, h);
        PRED_ADD2(rs[2], pm, 2, h);
        PRED_ADD2(rs[3], pm, 3, h);
    }
}

// sobel + octant + pack for one hist element; p = top-left of 3x3 in xs
static __device__ __forceinline__ u64 hist_val(const float* __restrict__ p) {
    float a00 = p[0],       a01 = p[1],           a02 = p[2];
    float a10 = p[XP2],     a12 = p[XP2 + 2];
    float a20 = p[2 * XP2], a21 = p[2 * XP2 + 1], a22 = p[2 * XP2 + 2];
    float S0 = a00 + 2.0f * a10 + a20;
    float S2 = a02 + 2.0f * a12 + a22;
    float D0 = a20 - a00;
    float D1 = a21 - a01;
    float D2 = a22 - a02;
    float dx = S2 - S0;
    float dy = D0 + 2.0f * D1 + D2;

    float sq = dx * dx + dy * dy;
    float sg = fmaxf(sq, 1.17549435e-38f);
    float rs_;
    asm("rsqrt.approx.f32 %0, %1;" : "=f"(rs_) : "f"(sg));
    float mag = sq * rs_;

    // octant of atan2(dy,dx) via sign bits + |dy|>|dx|; tie rules match
    // strict-> first-occurrence argmax of the 8 cosine projections.
    u32 bx = __float_as_uint(dx);
    u32 by = __float_as_uint(dy);
    u32 b2 = by >> 31;
    u32 b1 = (bx ^ by) >> 31;
    u32 c  = (fabsf(dy) > fabsf(dx)) ? 1u : 0u;
    u32 b0 = c ^ b1;
    u32 idx = (b2 << 2) | (b1 << 1) | b0;

    u32 magb = __float_as_uint(mag) & 0xFFFFFFFCu;
    u32 pm   = idx >> 1;
    u32 lo, hi;
    if (idx & 1) { lo = pm;        hi = magb; }
    else         { lo = magb | pm; hi = 0u;   }
    return ((u64)hi << 32) | lo;
}

__global__ __launch_bounds__(256)
void sift_fused13_kernel(const float* __restrict__ x, float* __restrict__ out)
{
    extern __shared__ char smem[];
    float* xs = (float*)smem;
    u64*   hs = (u64*)(smem + XS_BYTES);

    const int tid = threadIdx.x;
    const int ox0 = blockIdx.x * TX;
    const int oy0 = blockIdx.y * TY;

    // ---- phase 1: load x tile (cols gx = ox0-4+c, rows gy = oy0-3+r), zero-padded
    const bool ld_interior = (ox0 >= 4) && (ox0 <= IMG - 132) &&
                             (oy0 >= 3) && (oy0 <= IMG - 34);
    if (ld_interior) {
        // e = r*34 + c4 over XR*34 = 1258 float4s; incremental index tracking.
        // e += 256 => r += 7, c4 += 18; carry: c4 -= 34, r += 1.
        // dst stride: 7*136 + 4*18 = 1024 floats, carry delta 136 - 136 = 0.
        int r  = tid / 34;
        int c4 = tid - r * 34;
        const float* src = x + (oy0 - 3 + r) * IMG + (ox0 - 4) + 4 * c4;
        float*       dst = xs + r * XP2 + 4 * c4;
        for (int e = tid; e < XR * 34; e += 256) {
            *(float4*)dst = *(const float4*)src;
            src += 7 * IMG + 72;
            dst += 1024;
            c4  += 18;
            if (c4 >= 34) { c4 -= 34; src += IMG - 136; }
        }
    } else {
        for (int e = tid; e < XR * XP2; e += 256) {
            int r  = e / XP2;
            int c  = e - r * XP2;
            int gy = oy0 - 3 + r;
            int gx = ox0 - 4 + c;
            float v = 0.0f;
            if ((unsigned)gy < (unsigned)IMG && (unsigned)gx < (unsigned)IMG)
                v = x[gy * IMG + gx];
            xs[r * XP2 + c] = v;
        }
    }
    __syncthreads();

    // ---- phase 2: sobel -> octant -> pre-routed packed pair.
    const bool h_interior = (ox0 >= 2) && (ox0 + TX + 2 < IMG) &&
                            (oy0 >= 2) && (oy0 + TY + 2 < IMG);
    if (h_interior) {
        // e = hy*131 + hx; e += 256 => hy += 1, hx += 125 (carry: hx -= 131, hy += 1)
        // xs offset = hy*136 + hx + 1: += 261, carry extra +5.
        int hy = tid / 131;
        int hx = tid - hy * 131;
        const float* px = xs + hy * XP2 + hx + 1;
        u64* hp = hs + tid;
        u64* const hend = hs + HR * HP;
        for (; hp < hend; hp += 256) {
            *hp = hist_val(px);
            hx += 125;
            px += 261;
            if (hx >= 131) { hx -= 131; px += 5; }
        }
    } else {
        for (int e = tid; e < HR * HP; e += 256) {
            int hy = e / HP;
            int hx = e - hy * HP;
            int gy = oy0 - 2 + hy;
            int gx = ox0 - 2 + hx;
            u64 pv = 0ull;
            if ((unsigned)gy < (unsigned)IMG && (unsigned)gx < (unsigned)IMG)
                pv = hist_val(xs + hy * XP2 + hx + 1);
            hs[e] = pv;
        }
    }
    __syncthreads();

    // ---- phase 3: 4x4 box sum, vertical sliding window, 4 packed-pair channels
    const int tx   = tid & (TX - 1);
    const int q    = tid >> 7;              // 0/1 -> tile half in y
    const int ox   = ox0 + tx;
    const int oy_s = oy0 + q * HTY;
    const bool oxok = (ox < OUT);
    const u64* hb = hs + tx;
    const int hy0 = q * HTY;

    const u64 NEG1 = 0xBF800000BF800000ull;  // {-1.0f, -1.0f}

    u64 row[4][4];
    u64 acc[4];
#pragma unroll
    for (int pp = 0; pp < 4; ++pp) acc[pp] = 0ull;
#pragma unroll
    for (int k = 0; k < 4; ++k) {
#pragma unroll
        for (int pp = 0; pp < 4; ++pp) row[k][pp] = 0ull;
        accum_row(hb + (hy0 + k) * HP, row[k]);
#pragma unroll
        for (int pp = 0; pp < 4; ++pp) ADD2(acc[pp], acc[pp], row[k][pp]);
    }

#pragma unroll 4
    for (int i = 0; i < HTY; ++i) {
        int oy = oy_s + i;
        if (oxok && oy < OUT) {
            int base = oy * OUT + ox;
#pragma unroll
            for (int pp = 0; pp < 4; ++pp) {
                u32 lo = (u32)acc[pp];
                u32 hi = (u32)(acc[pp] >> 32);
                out[(2 * pp)     * OPLANE + base] = __uint_as_float(lo);
                out[(2 * pp + 1) * OPLANE + base] = __uint_as_float(hi);
            }
        }
        if (i < HTY - 1) {
            u64 nr[4];
#pragma unroll
            for (int pp = 0; pp < 4; ++pp) nr[pp] = 0ull;
            accum_row(hb + (hy0 + 4 + i) * HP, nr);
            const int k = i & 3;
#pragma unroll
            for (int pp = 0; pp < 4; ++pp) {
                u64 t;
                ADD2(t, acc[pp], nr[pp]);            // acc + new
                FMA2(acc[pp], row[k][pp], NEG1, t);  // - old
                row[k][pp] = nr[pp];
            }
        }
    }
}

extern "C" void kernel_launch(void* const* d_in, const int* in_sizes, int n_in,
                              void* d_out, int out_size)
{
    (void)in_sizes; (void)n_in; (void)out_size;
    const float* x = (const float*)d_in[0];
    float* out = (float*)d_out;
    cudaFuncSetAttribute(sift_fused13_kernel,
                         cudaFuncAttributeMaxDynamicSharedMemorySize, SMEM_BYTES);
    dim3 grid((OUT + TX - 1) / TX, (OUT + TY - 1) / TY);  // 33 x 129
    sift_fused13_kernel<<<grid, 256, SMEM_BYTES>>>(x, out);
}